// round 15
// baseline (speedup 1.0000x reference)
#include <cuda_runtime.h>

#define BATCH 4
#define HEADS 8
#define MID 16
#define G 4
#define COUT 64
#define WDIM 28
#define NPOS 784
#define NREL 110
#define QLOG2 0.8329091229351039f   // (1/sqrt(3)) * log2(e)

typedef unsigned long long ull;
typedef unsigned int uint;

__device__ __forceinline__ float ex2_(float x){ float r; asm("ex2.approx.f32 %0,%1;":"=f"(r):"f"(x)); return r; }
__device__ __forceinline__ uint tf32_(float f){ uint u; asm("cvt.rna.tf32.f32 %0,%1;":"=r"(u):"f"(f)); return u; }
__device__ __forceinline__ ull pk2(float lo, float hi){ ull r; asm("mov.b64 %0,{%1,%2};":"=l"(r):"f"(lo),"f"(hi)); return r; }
__device__ __forceinline__ void upk2(ull v, float& lo, float& hi){ asm("mov.b64 {%0,%1},%2;":"=f"(lo),"=f"(hi):"l"(v)); }
__device__ __forceinline__ ull fma2_(ull a, ull b, ull c){ ull d; asm("fma.rn.f32x2 %0,%1,%2,%3;":"=l"(d):"l"(a),"l"(b),"l"(c)); return d; }

#define MMA_TF32(d0,d1,d2,d3,a0,a1,a2,a3,b0,b1) \
    asm volatile("mma.sync.aligned.m16n8k8.row.col.f32.tf32.tf32.f32 " \
        "{%0,%1,%2,%3},{%4,%5,%6,%7},{%8,%9},{%0,%1,%2,%3};" \
        : "+f"(d0),"+f"(d1),"+f"(d2),"+f"(d3) \
        : "r"(a0),"r"(a1),"r"(a2),"r"(a3),"r"(b0),"r"(b1))

// ---------------- device scratch ----------------
__device__ float d_outv[BATCH*G*NPOS*(MID*HEADS)];   // [b][g][pos][m*8+h]

// ---------------- fused attention: qkv + embed + TC attention ----------------
// smem float offsets
#define SM_K    0            // [28][16][33] = 14784
#define SM_V    14784        // [28][32][16] = 14336 (tf32 bits, col-swizzled)
#define SM_S    29120        // [2 groups][3 bufs][32][36] = 6912
#define SM_FR   36032        // [32][112]
#define SM_FC   39616        // [32][112]
#define SM_Q    43200        // [32][16]
#define SM_NM   43712        // [32]
#define SM_EX   43744        // [8 warps][32 lanes][10] = 2560
#define SM_CTRL 46304
#define SM_ER   46308        // [110][8] = 880
#define SM_EC   47188        // [110][8] = 880
#define SM_X    48068        // [3][784] = 2352
#define SM_WQ   50420        // [384]
#define SM_WK   50804        // [384]
#define SM_WV   51188        // [384]
#define SM_BQ   51572        // [128]
#define SM_BK   51700        // [128]
#define SM_BV   51828        // [128]
#define SM_TOT  51956
#define ATTN_SMEM_BYTES (SM_TOT*4)

__global__ void __launch_bounds__(512, 1) attn_kernel(
    const float* __restrict__ x,
    const float* __restrict__ wq, const float* __restrict__ bq,
    const float* __restrict__ wk, const float* __restrict__ bk,
    const float* __restrict__ wv, const float* __restrict__ bv,
    const float* __restrict__ w1r, const float* __restrict__ b1r,
    const float* __restrict__ gr,  const float* __restrict__ ber,
    const float* __restrict__ w2r, const float* __restrict__ b2r,
    const float* __restrict__ w1c, const float* __restrict__ b1c,
    const float* __restrict__ gc,  const float* __restrict__ bec,
    const float* __restrict__ w2c, const float* __restrict__ b2c)
{
    extern __shared__ float sm[];
    float* Ksh  = sm + SM_K;
    float* Vsh  = sm + SM_V;
    float* Sb   = sm + SM_S;
    float* fRs  = sm + SM_FR;
    float* fCs  = sm + SM_FC;
    float* Qs   = sm + SM_Q;
    float* nM   = sm + SM_NM;
    float* EX   = sm + SM_EX;
    float* Ersh = sm + SM_ER;
    float* Ecsh = sm + SM_EC;
    float* Xsh  = sm + SM_X;
    float* Wq   = sm + SM_WQ;
    float* Wk   = sm + SM_WK;
    float* Wv   = sm + SM_WV;
    float* Bq   = sm + SM_BQ;
    float* Bk   = sm + SM_BK;
    float* Bv   = sm + SM_BV;
    int*  ctrl  = (int*)(sm + SM_CTRL);

    int t = threadIdx.x;
    int w = t >> 5, lane = t & 31, grp = lane >> 2, tig = lane & 3;
    int gid = w >> 3;          // kk-group
    int wl  = w & 7;
    int bx = blockIdx.x;
    int i0 = (bx % 14) * 2;    // i-pair {i0, i0+1}
    int bh = bx / 14;
    int b  = bh >> 3, h = bh & 7;

    if (t == 0) *ctrl = 0;

    // ---- load x slice + qkv weights into smem ----
    {
        const float4* xg = (const float4*)(x + (size_t)b*3*NPOS);
        for (int idx = t; idx < 588; idx += 512) ((float4*)Xsh)[idx] = xg[idx];
        if (t < 96)        ((float4*)Wq)[t] = ((const float4*)wq)[t];
        else if (t < 192)  ((float4*)Wk)[t-96]  = ((const float4*)wk)[t-96];
        else if (t < 288)  ((float4*)Wv)[t-192] = ((const float4*)wv)[t-192];
        else if (t < 320)  ((float4*)Bq)[t-288] = ((const float4*)bq)[t-288];
        else if (t < 352)  ((float4*)Bk)[t-320] = ((const float4*)bk)[t-320];
        else if (t < 384)  ((float4*)Bv)[t-352] = ((const float4*)bv)[t-352];
    }

    // ---- embedding MLP into smem tables (220 rows) ----
    if (t >= 256 && t < 256 + 2*NREL) {
        int tt = t - 256;
        bool isRow = (tt < NREL);
        int a = isRow ? tt : tt - NREL;
        const float* w1 = isRow ? w1r : w1c;
        const float* b1 = isRow ? b1r : b1c;
        const float* ga = isRow ? gr  : gc;
        const float* be = isRow ? ber : bec;
        const float* w2 = isRow ? w2r : w2c;
        const float* b2 = isRow ? b2r : b2c;

        float u;
        if (a < 55) u = a * (2.0f/54.0f) - 1.0f;
        else        u = -((a-55) * (2.0f/54.0f) - 1.0f);

        float hh[16];
        float mu = 0.f;
#pragma unroll
        for (int c = 0; c < 16; c++) { hh[c] = u*w1[c] + b1[c]; mu += hh[c]; }
        mu *= (1.0f/16.0f);
        float var = 0.f;
#pragma unroll
        for (int c = 0; c < 16; c++) { float d = hh[c]-mu; var += d*d; }
        var *= (1.0f/16.0f);
        float inv = rsqrtf(var + 1e-5f);
#pragma unroll
        for (int c = 0; c < 16; c++) {
            float hn = ga[c]*(hh[c]-mu)*inv + be[c];
            hh[c] = hn / (1.0f + expf(-hn));
        }
        float* out = isRow ? Ersh : Ecsh;
#pragma unroll
        for (int d = 0; d < 8; d++) {
            float s = b2[d];
#pragma unroll
            for (int c = 0; c < 16; c++) s += hh[c]*w2[d*16+c];
            out[a*8 + d] = s;
        }
    }

    // targeted padding zero: K cols 28..32 of each 33-wide row; V rows ll 28..31
    for (int idx = t; idx < 2240; idx += 512) {
        int row = idx / 5, c = idx - row*5;
        Ksh[row*33 + 28 + c] = 0.f;
    }
    for (int idx = t; idx < 1792; idx += 512) {
        int kk = idx >> 6, r = idx & 63;
        Vsh[(kk*32 + 28)*16 + r] = 0.f;
    }
    __syncthreads();

    // ---- compute K/V from x (fused qkv conv) ----
    for (int idx = t; idx < 3136; idx += 512) {
        int mg = idx & 3, pos = idx >> 2;
        int kk = pos / 28, ll = pos - kk*28;
        float x0 = Xsh[pos], x1 = Xsh[NPOS + pos], x2 = Xsh[2*NPOS + pos];
        float kvals[4];
        float4 vv;
        float* vp = (float*)&vv;
#pragma unroll
        for (int mi = 0; mi < 4; mi++) {
            int o = (mg*4 + mi)*8 + h;
            kvals[mi] = Bk[o] + Wk[o*3+0]*x0 + Wk[o*3+1]*x1 + Wk[o*3+2]*x2;
            vp[mi]    = Bv[o] + Wv[o*3+0]*x0 + Wv[o*3+1]*x1 + Wv[o*3+2]*x2;
        }
        float* kb = Ksh + (kk*16 + mg*4)*33 + ll;
        kb[0] = kvals[0]; kb[33] = kvals[1]; kb[66] = kvals[2]; kb[99] = kvals[3];
        vv.x = __uint_as_float(tf32_(vv.x));
        vv.y = __uint_as_float(tf32_(vv.y));
        vv.z = __uint_as_float(tf32_(vv.z));
        vv.w = __uint_as_float(tf32_(vv.w));
        int sw = ((ll >> 1) & 1) << 1;
        ((float4*)(Vsh + (kk*32 + ll)*16))[mg ^ sw] = vv;
    }
    __syncthreads();

    // max ||k||^2 (once per bh)
    {
        float mx = 0.f;
        for (int pos = t; pos < NPOS; pos += 512) {
            int kk = pos / 28, ll = pos - kk*28;
            float n2 = 0.f;
#pragma unroll
            for (int c = 0; c < 16; c++) { float kv = Ksh[(kk*16+c)*33 + ll]; n2 += kv*kv; }
            mx = fmaxf(mx, n2);
        }
#pragma unroll
        for (int off = 16; off; off >>= 1) mx = fmaxf(mx, __shfl_xor_sync(~0u, mx, off));
        if (lane == 0) atomicMax(ctrl, __float_as_int(mx));
    }
    __syncthreads();
    float maxknorm = sqrtf(__int_as_float(*ctrl));

    // role constants (i-independent)
    int mt_p = wl >> 2, nt_p = wl & 3;
    int g_c = wl >> 1, mt_c = wl & 1;
    const float* stab = (g_c == 0 || g_c == 2) ? fRs : fCs;
    int soff = (g_c >= 2) ? 55 : 0;
    int j0 = mt_c*16 + grp, j1 = j0 + 8;
    int sbase_p = gid*3456 + mt_p*576 + nt_p*8;
    int sbase_c = gid*3456 + mt_c*576;
    int kk0 = gid*14;
    int barid = gid + 1;
    int s8 = (tig & 2) << 2;   // V col swizzle for this lane's rows

    for (int ii = 0; ii < 2; ii++) {
        int i = i0 + ii;

        // ---- per-i: compute Q from x (scaled to log2 domain) ----
        {
            int row = t >> 4, ch = t & 15;
            float qv = 0.f;
            if (row < 28) {
                int pos = i*28 + row;
                int o = ch*8 + h;
                float x0 = Xsh[pos], x1 = Xsh[NPOS + pos], x2 = Xsh[2*NPOS + pos];
                qv = (Bq[o] + Wq[o*3+0]*x0 + Wq[o*3+1]*x1 + Wq[o*3+2]*x2) * QLOG2;
            }
            Qs[t & 511] = qv;
        }
        __syncthreads();

        // per-row tables fR/fC (from smem-cached embeddings)
        for (int idx = t; idx < 32*110; idx += 512) {
            int j = idx / 110, a = idx - j*110;
            const float4* er = (const float4*)(Ersh + a*8);
            const float4* ec = (const float4*)(Ecsh + a*8);
            float4 e0 = er[0], e1 = er[1], c0 = ec[0], c1 = ec[1];
            const float* q = Qs + j*16;
            float fr = q[0]*e0.x + q[1]*e0.y + q[2]*e0.z + q[3]*e0.w
                     + q[4]*e1.x + q[5]*e1.y + q[6]*e1.z + q[7]*e1.w;
            float fc = q[8]*c0.x + q[9]*c0.y + q[10]*c0.z + q[11]*c0.w
                     + q[12]*c1.x + q[13]*c1.y + q[14]*c1.z + q[15]*c1.w;
            fRs[j*112 + a] = fr;
            fCs[j*112 + a] = fc;
        }
        __syncthreads();
        // parallel nM: thread (j = t>>4, s = t&15)
        {
            int j = t >> 4, s = t & 15;
            float q = Qs[j*16 + s];
            float qn = q*q;
            float mR = -1e30f, mC = -1e30f;
            for (int a = s; a < NREL; a += 16) {
                mR = fmaxf(mR, fRs[j*112 + a]);
                mC = fmaxf(mC, fCs[j*112 + a]);
            }
#pragma unroll
            for (int off = 8; off; off >>= 1) {
                qn += __shfl_xor_sync(~0u, qn, off);
                mR = fmaxf(mR, __shfl_xor_sync(~0u, mR, off));
                mC = fmaxf(mC, __shfl_xor_sync(~0u, mC, off));
            }
            if (s == 0) nM[j] = -(sqrtf(qn)*maxknorm + mR + mC + 0.25f);
        }
        __syncthreads();

        // ---- producer frags ----
        uint qhi[2][4], qlo[2][4];
#pragma unroll
        for (int kc = 0; kc < 2; kc++) {
#pragma unroll
            for (int e = 0; e < 4; e++) {
                int r = grp + (e & 1)*8;
                int c = kc*8 + tig + (e >> 1)*4;
                float f = Qs[(mt_p*16 + r)*16 + c];
                uint hi = tf32_(f);
                qhi[kc][e] = hi;
                qlo[kc][e] = tf32_(f - __uint_as_float(hi));
            }
        }

        // ---- consumer constants ----
        float nm0 = nM[j0], nm1 = nM[j1];
        float tpr[4][4];
#pragma unroll
        for (int ch = 0; ch < 4; ch++) {
#pragma unroll
            for (int e = 0; e < 4; e++) {
                int j  = (e & 1) ? j1 : j0;
                int ll = ch*8 + tig + (e >> 1)*4;
                float tv;
                if (ll >= 28) tv = -1e30f;
                else {
                    int C = ll - j + 27;
                    C = max(0, min(54, C));
                    float v;
                    if      (g_c == 0) v = fCs[j*112 + C];
                    else if (g_c == 1) v = fRs[j*112 + C + 55];
                    else if (g_c == 2) v = fCs[j*112 + C + 55];
                    else               v = fRs[j*112 + C];
                    tv = v + ((e & 1) ? nm1 : nm0);
                }
                tpr[ch][e] = tv;
            }
        }

        float o0_0=0,o0_1=0,o0_2=0,o0_3=0;
        float o1_0=0,o1_1=0,o1_2=0,o1_3=0;
        float su0 = 0.f, su1 = 0.f;

        auto produceS = [&](int kk, int buf) {
            float s0=0.f, s1=0.f, s2=0.f, s3=0.f;
#pragma unroll
            for (int kc = 0; kc < 2; kc++) {
                const float* kp = Ksh + (kk*16 + kc*8 + tig)*33 + nt_p*8 + grp;
                float f0 = kp[0], f1 = kp[4*33];
                uint bh0 = tf32_(f0), bh1 = tf32_(f1);
                uint bl0 = tf32_(f0 - __uint_as_float(bh0));
                uint bl1 = tf32_(f1 - __uint_as_float(bh1));
                MMA_TF32(s0,s1,s2,s3, qhi[kc][0],qhi[kc][1],qhi[kc][2],qhi[kc][3], bh0,bh1);
                MMA_TF32(s0,s1,s2,s3, qhi[kc][0],qhi[kc][1],qhi[kc][2],qhi[kc][3], bl0,bl1);
                MMA_TF32(s0,s1,s2,s3, qlo[kc][0],qlo[kc][1],qlo[kc][2],qlo[kc][3], bh0,bh1);
            }
            float* sp = Sb + sbase_p + buf*1152;
            *(float2*)(sp + grp*36 + 2*tig)     = make_float2(s0, s1);
            *(float2*)(sp + (grp+8)*36 + 2*tig) = make_float2(s2, s3);
        };

        auto consumeS = [&](int kk, int buf) {
            int sidx = kk - i + 27 + soff;
            float sj0 = stab[j0*112 + sidx];
            float sj1 = stab[j1*112 + sidx];
            const float* sc = Sb + sbase_c + buf*1152;
            const float* vb = Vsh + kk*512;
#pragma unroll
            for (int ch = 0; ch < 4; ch++) {
                float l0 = sc[grp*36     + ch*8 + tig];
                float l1 = sc[(grp+8)*36 + ch*8 + tig];
                float l2 = sc[grp*36     + ch*8 + tig + 4];
                float l3 = sc[(grp+8)*36 + ch*8 + tig + 4];
                float e0 = ex2_(l0 + sj0 + tpr[ch][0]);
                float e1 = ex2_(l1 + sj1 + tpr[ch][1]);
                float e2 = ex2_(l2 + sj0 + tpr[ch][2]);
                float e3 = ex2_(l3 + sj1 + tpr[ch][3]);
                uint p0 = tf32_(e0), p1 = tf32_(e1), p2 = tf32_(e2), p3 = tf32_(e3);
                su0 += __uint_as_float(p0) + __uint_as_float(p2);
                su1 += __uint_as_float(p1) + __uint_as_float(p3);
                const float* vp = vb + (ch*8 + tig)*16;
                uint v00 = __float_as_uint(vp[grp ^ s8]);
                uint v10 = __float_as_uint(vp[(grp+8) ^ s8]);
                uint v01 = __float_as_uint(vp[64 + (grp ^ s8)]);
                uint v11 = __float_as_uint(vp[64 + ((grp+8) ^ s8)]);
                MMA_TF32(o0_0,o0_1,o0_2,o0_3, p0,p1,p2,p3, v00,v01);
                MMA_TF32(o1_0,o1_1,o1_2,o1_3, p0,p1,p2,p3, v10,v11);
            }
        };

        // skew-2 pipeline
        produceS(kk0 + 0, 0);
        produceS(kk0 + 1, 1);
        asm volatile("bar.sync %0, 256;" :: "r"(barid) : "memory");
        int bufp = 2, bufc = 0;
#pragma unroll 2
        for (int kx = 0; kx < 14; kx++) {
            if (kx < 12) produceS(kk0 + kx + 2, bufp);
            consumeS(kk0 + kx, bufc);
            if (++bufp == 3) bufp = 0;
            if (++bufc == 3) bufc = 0;
            asm volatile("bar.sync %0, 256;" :: "r"(barid) : "memory");
        }

        // ---- row sums within group ----
        su0 += __shfl_xor_sync(~0u, su0, 1); su0 += __shfl_xor_sync(~0u, su0, 2);
        su1 += __shfl_xor_sync(~0u, su1, 1); su1 += __shfl_xor_sync(~0u, su1, 2);

        // ---- combine groups ----
        __syncthreads();
        if (gid == 1) {
            float* e = EX + (wl*32 + lane)*10;
            e[0]=o0_0; e[1]=o0_1; e[2]=o0_2; e[3]=o0_3;
            e[4]=o1_0; e[5]=o1_1; e[6]=o1_2; e[7]=o1_3;
            e[8]=su0;  e[9]=su1;
        }
        __syncthreads();
        if (gid == 0) {
            const float* e = EX + (wl*32 + lane)*10;
            o0_0+=e[0]; o0_1+=e[1]; o0_2+=e[2]; o0_3+=e[3];
            o1_0+=e[4]; o1_1+=e[5]; o1_2+=e[6]; o1_3+=e[7];
            su0 +=e[8]; su1 +=e[9];

            float inv0, inv1;
            asm("rcp.approx.f32 %0,%1;" : "=f"(inv0) : "f"(su0));
            asm("rcp.approx.f32 %0,%1;" : "=f"(inv1) : "f"(su1));

            size_t obase = ((size_t)(b*G + g_c)*NPOS + i*28)*128 + h;
            {
                size_t rb = obase + (size_t)j0*128;
                int m0 = 2*tig;
                d_outv[rb + (m0  )*8] = o0_0*inv0;
                d_outv[rb + (m0+1)*8] = o0_1*inv0;
                d_outv[rb + (m0+8)*8] = o1_0*inv0;
                d_outv[rb + (m0+9)*8] = o1_1*inv0;
            }
            if (j1 < 28) {
                size_t rb = obase + (size_t)j1*128;
                int m0 = 2*tig;
                d_outv[rb + (m0  )*8] = o0_2*inv1;
                d_outv[rb + (m0+1)*8] = o0_3*inv1;
                d_outv[rb + (m0+8)*8] = o1_2*inv1;
                d_outv[rb + (m0+9)*8] = o1_3*inv1;
            }
        }
        __syncthreads();   // protect Qs/tables before next ii
    }
}

// ---------------- output 1x1 conv, FFMA2 tiled SGEMM (64x64, 196 blocks) ----------------
#define OPAD 68
#define OUT_SMEM_BYTES (2*128*OPAD*4)
__global__ void __launch_bounds__(256, 2) out_gemm(const float* __restrict__ wout,
                                                   const float* __restrict__ bout,
                                                   float* __restrict__ out)
{
    extern __shared__ float osh[];
    float* Xs = osh;               // [k][r], stride OPAD
    float* Ws = osh + 128*OPAD;    // [k][c], stride OPAD

    int t = threadIdx.x;
    int Rbase = blockIdx.x * 64;

    for (int idx = t; idx < 2048; idx += 256) {
        int r = idx & 63, c4 = idx >> 6;
        float4 val = ((const float4*)d_outv)[(size_t)(Rbase + r)*32 + c4];
        Xs[(4*c4+0)*OPAD + r] = val.x;
        Xs[(4*c4+1)*OPAD + r] = val.y;
        Xs[(4*c4+2)*OPAD + r] = val.z;
        Xs[(4*c4+3)*OPAD + r] = val.w;
    }
    for (int idx = t; idx < 2048; idx += 256) {
        int o = idx & 63, c4 = idx >> 6;
        float4 val = ((const float4*)wout)[o*32 + c4];
        Ws[(4*c4+0)*OPAD + o] = val.x;
        Ws[(4*c4+1)*OPAD + o] = val.y;
        Ws[(4*c4+2)*OPAD + o] = val.z;
        Ws[(4*c4+3)*OPAD + o] = val.w;
    }
    __syncthreads();

    int tx = t & 15, ty = t >> 4;
    ull a0c01=0, a0c23=0, a1c01=0, a1c23=0, a2c01=0, a2c23=0, a3c01=0, a3c23=0;

#pragma unroll 8
    for (int k = 0; k < 128; k++) {
        float4 av = *(const float4*)&Xs[k*OPAD + 4*tx];
        ulonglong2 bv = *(const ulonglong2*)&Ws[k*OPAD + 4*ty];
        ull ab0 = pk2(av.x, av.x), ab1 = pk2(av.y, av.y);
        ull ab2 = pk2(av.z, av.z), ab3 = pk2(av.w, av.w);
        a0c01 = fma2_(ab0, bv.x, a0c01);  a0c23 = fma2_(ab0, bv.y, a0c23);
        a1c01 = fma2_(ab1, bv.x, a1c01);  a1c23 = fma2_(ab1, bv.y, a1c23);
        a2c01 = fma2_(ab2, bv.x, a2c01);  a2c23 = fma2_(ab2, bv.y, a2c23);
        a3c01 = fma2_(ab3, bv.x, a3c01);  a3c23 = fma2_(ab3, bv.y, a3c23);
    }

    float vals[4][4];
    upk2(a0c01, vals[0][0], vals[0][1]);  upk2(a0c23, vals[0][2], vals[0][3]);
    upk2(a1c01, vals[1][0], vals[1][1]);  upk2(a1c23, vals[1][2], vals[1][3]);
    upk2(a2c01, vals[2][0], vals[2][1]);  upk2(a2c23, vals[2][2], vals[2][3]);
    upk2(a3c01, vals[3][0], vals[3][1]);  upk2(a3c23, vals[3][2], vals[3][3]);

    int R0 = Rbase + 4*tx;
    int bb = R0 / (G*NPOS);
    int rem = R0 - bb*(G*NPOS);
    int g = rem / NPOS;
    int pos = rem - g*NPOS;

#pragma unroll
    for (int ci = 0; ci < 4; ci++) {
        int o = 4*ty + ci;
        float bi = bout[o];
        float4 v = make_float4(vals[0][ci] + bi, vals[1][ci] + bi,
                               vals[2][ci] + bi, vals[3][ci] + bi);
        *(float4*)&out[(((size_t)(bb*COUT + o))*G + g)*NPOS + pos] = v;
    }
}

// ---------------- launch ----------------
extern "C" void kernel_launch(void* const* d_in, const int* in_sizes, int n_in,
                              void* d_out, int out_size)
{
    const float* x     = (const float*)d_in[0];
    const float* wq    = (const float*)d_in[1];
    const float* bq    = (const float*)d_in[2];
    const float* wk    = (const float*)d_in[3];
    const float* bk    = (const float*)d_in[4];
    const float* wv    = (const float*)d_in[5];
    const float* bv    = (const float*)d_in[6];
    const float* w_out = (const float*)d_in[7];
    const float* b_out = (const float*)d_in[8];
    const float* row_w1 = (const float*)d_in[9];
    const float* row_b1 = (const float*)d_in[10];
    const float* row_g  = (const float*)d_in[11];
    const float* row_be = (const float*)d_in[12];
    const float* row_w2 = (const float*)d_in[13];
    const float* row_b2 = (const float*)d_in[14];
    const float* col_w1 = (const float*)d_in[15];
    const float* col_b1 = (const float*)d_in[16];
    const float* col_g  = (const float*)d_in[17];
    const float* col_be = (const float*)d_in[18];
    const float* col_w2 = (const float*)d_in[19];
    const float* col_b2 = (const float*)d_in[20];

    cudaFuncSetAttribute(attn_kernel, cudaFuncAttributeMaxDynamicSharedMemorySize, ATTN_SMEM_BYTES);
    cudaFuncSetAttribute(out_gemm,    cudaFuncAttributeMaxDynamicSharedMemorySize, OUT_SMEM_BYTES);

    attn_kernel<<<BATCH*HEADS*14, 512, ATTN_SMEM_BYTES>>>(
        x, wq, bq, wk, bk, wv, bv,
        row_w1, row_b1, row_g, row_be, row_w2, row_b2,
        col_w1, col_b1, col_g, col_be, col_w2, col_b2);

    out_gemm<<<196, 256, OUT_SMEM_BYTES>>>(w_out, b_out, (float*)d_out);
}

// round 16
// speedup vs baseline: 1.0666x; 1.0666x over previous
#include <cuda_runtime.h>

#define BATCH 4
#define HEADS 8
#define MID 16
#define G 4
#define COUT 64
#define WDIM 28
#define NPOS 784
#define NREL 110
#define QLOG2 0.8329091229351039f   // (1/sqrt(3)) * log2(e)

typedef unsigned long long ull;
typedef unsigned int uint;

__device__ __forceinline__ float ex2_(float x){ float r; asm("ex2.approx.f32 %0,%1;":"=f"(r):"f"(x)); return r; }
__device__ __forceinline__ uint tf32_(float f){ uint u; asm("cvt.rna.tf32.f32 %0,%1;":"=r"(u):"f"(f)); return u; }
__device__ __forceinline__ ull pk2(float lo, float hi){ ull r; asm("mov.b64 %0,{%1,%2};":"=l"(r):"f"(lo),"f"(hi)); return r; }
__device__ __forceinline__ void upk2(ull v, float& lo, float& hi){ asm("mov.b64 {%0,%1},%2;":"=f"(lo),"=f"(hi):"l"(v)); }
__device__ __forceinline__ ull fma2_(ull a, ull b, ull c){ ull d; asm("fma.rn.f32x2 %0,%1,%2,%3;":"=l"(d):"l"(a),"l"(b),"l"(c)); return d; }

#define MMA_TF32(d0,d1,d2,d3,a0,a1,a2,a3,b0,b1) \
    asm volatile("mma.sync.aligned.m16n8k8.row.col.f32.tf32.tf32.f32 " \
        "{%0,%1,%2,%3},{%4,%5,%6,%7},{%8,%9},{%0,%1,%2,%3};" \
        : "+f"(d0),"+f"(d1),"+f"(d2),"+f"(d3) \
        : "r"(a0),"r"(a1),"r"(a2),"r"(a3),"r"(b0),"r"(b1))

// ---------------- device scratch ----------------
__device__ float d_q[BATCH*HEADS*NPOS*MID];   // [bh][pos][16]
__device__ float d_k[BATCH*HEADS*NPOS*MID];
__device__ float d_v[BATCH*HEADS*NPOS*MID];
__device__ float d_Er[NREL*8];
__device__ float d_Ec[NREL*8];
__device__ float d_outv[BATCH*G*NPOS*(MID*HEADS)];   // [b][g][pos][m*8+h]

// ---------------- fused q/k/v conv + embedding MLP (extra block) ----------------
__global__ void qkv_embed_kernel(
    const float* __restrict__ x,
    const float* __restrict__ wq, const float* __restrict__ bq,
    const float* __restrict__ wk, const float* __restrict__ bk,
    const float* __restrict__ wv, const float* __restrict__ bv,
    const float* __restrict__ w1r, const float* __restrict__ b1r,
    const float* __restrict__ gr,  const float* __restrict__ ber,
    const float* __restrict__ w2r, const float* __restrict__ b2r,
    const float* __restrict__ w1c, const float* __restrict__ b1c,
    const float* __restrict__ gc,  const float* __restrict__ bec,
    const float* __restrict__ w2c, const float* __restrict__ b2c)
{
    if (blockIdx.x == 392) {
        int t = threadIdx.x;
        if (t >= 2*NREL) return;
        bool isRow = (t < NREL);
        int a = isRow ? t : t - NREL;
        const float* w1 = isRow ? w1r : w1c;
        const float* b1 = isRow ? b1r : b1c;
        const float* ga = isRow ? gr  : gc;
        const float* be = isRow ? ber : bec;
        const float* w2 = isRow ? w2r : w2c;
        const float* b2 = isRow ? b2r : b2c;

        float u;
        if (a < 55) u = a * (2.0f/54.0f) - 1.0f;
        else        u = -((a-55) * (2.0f/54.0f) - 1.0f);

        float h[16];
        float mu = 0.f;
#pragma unroll
        for (int c = 0; c < 16; c++) { h[c] = u*w1[c] + b1[c]; mu += h[c]; }
        mu *= (1.0f/16.0f);
        float var = 0.f;
#pragma unroll
        for (int c = 0; c < 16; c++) { float d = h[c]-mu; var += d*d; }
        var *= (1.0f/16.0f);
        float inv = rsqrtf(var + 1e-5f);
#pragma unroll
        for (int c = 0; c < 16; c++) {
            float hn = ga[c]*(h[c]-mu)*inv + be[c];
            h[c] = hn / (1.0f + expf(-hn));
        }
        float* out = isRow ? d_Er : d_Ec;
#pragma unroll
        for (int d = 0; d < 8; d++) {
            float s = b2[d];
#pragma unroll
            for (int c = 0; c < 16; c++) s += h[c]*w2[d*16+c];
            out[a*8 + d] = s;
        }
        return;
    }

    int idx = blockIdx.x*blockDim.x + threadIdx.x;
    if (idx >= BATCH*HEADS*NPOS*4) return;
    int mg  = idx & 3;
    int r   = idx >> 2;
    int pos = r % NPOS;
    int r2  = r / NPOS;
    int h   = r2 & 7;
    int b   = r2 >> 3;

    float x0 = x[(b*3+0)*NPOS + pos];
    float x1 = x[(b*3+1)*NPOS + pos];
    float x2 = x[(b*3+2)*NPOS + pos];

    float4 qv, kv, vv;
    float* qp = (float*)&qv; float* kp = (float*)&kv; float* vp = (float*)&vv;
#pragma unroll
    for (int mi = 0; mi < 4; mi++) {
        int o = (mg*4 + mi)*8 + h;
        qp[mi] = bq[o] + wq[o*3+0]*x0 + wq[o*3+1]*x1 + wq[o*3+2]*x2;
        kp[mi] = bk[o] + wk[o*3+0]*x0 + wk[o*3+1]*x1 + wk[o*3+2]*x2;
        vp[mi] = bv[o] + wv[o*3+0]*x0 + wv[o*3+1]*x1 + wv[o*3+2]*x2;
    }
    size_t dst4 = ((size_t)(b*HEADS + h)*NPOS + pos)*4 + mg;
    ((float4*)d_q)[dst4] = qv;
    ((float4*)d_k)[dst4] = kv;
    ((float4*)d_v)[dst4] = vv;
}

// ---------------- tf32 TC attention: persistent chunked, 148 CTAs ----------------
// smem float offsets
#define SM_K    0            // [28][16][33] = 14784
#define SM_V    14784        // [28][32][16] = 14336 (tf32 bits, col-swizzled)
#define SM_S    29120        // [2 groups][3 bufs][32][36] = 6912
#define SM_FR   36032        // [32][112]
#define SM_FC   39616        // [32][112]
#define SM_Q    43200        // [32][16]
#define SM_NM   43712        // [32]
#define SM_EX   43744        // [8 warps][32 lanes][10] = 2560
#define SM_CTRL 46304
#define SM_ER   46308        // [110][8] = 880
#define SM_EC   47188        // [110][8] = 880
#define SM_TOT  48068
#define ATTN_SMEM_BYTES (SM_TOT*4)

__global__ void __launch_bounds__(512, 1) attn_kernel()
{
    extern __shared__ float sm[];
    float* Ksh  = sm + SM_K;
    float* Vsh  = sm + SM_V;
    float* Sb   = sm + SM_S;
    float* fRs  = sm + SM_FR;
    float* fCs  = sm + SM_FC;
    float* Qs   = sm + SM_Q;
    float* nM   = sm + SM_NM;
    float* EX   = sm + SM_EX;
    float* Ersh = sm + SM_ER;
    float* Ecsh = sm + SM_EC;
    int*  ctrl  = (int*)(sm + SM_CTRL);

    int t = threadIdx.x;
    int w = t >> 5, lane = t & 31, grp = lane >> 2, tig = lane & 3;
    int gid = w >> 3;          // kk-group
    int wl  = w & 7;
    int c   = blockIdx.x;

    // static chunk: 8 CTAs x 7 units, 140 CTAs x 6 units (896 = 32 bh x 28 i)
    int cnt    = (c < 8) ? 7 : 6;
    int ustart = c*6 + min(c, 8);

    // cache Er/Ec in smem (once per CTA)
    if (t < 220) {
        ((float4*)Ersh)[t] = ((const float4*)d_Er)[t];
        ((float4*)Ecsh)[t] = ((const float4*)d_Ec)[t];
    }
    // targeted padding zero (once; pads never overwritten)
    for (int idx = t; idx < 2240; idx += 512) {
        int row = idx / 5, cc = idx - row*5;
        Ksh[row*33 + 28 + cc] = 0.f;
    }
    for (int idx = t; idx < 1792; idx += 512) {
        int kk = idx >> 6, r = idx & 63;
        Vsh[(kk*32 + 28)*16 + r] = 0.f;
    }

    // role constants
    int mt_p = wl >> 2, nt_p = wl & 3;
    int g_c = wl >> 1, mt_c = wl & 1;
    const float* stab = (g_c == 0 || g_c == 2) ? fRs : fCs;
    int soff = (g_c >= 2) ? 55 : 0;
    int j0 = mt_c*16 + grp, j1 = j0 + 8;
    int sbase_p = gid*3456 + mt_p*576 + nt_p*8;
    int sbase_c = gid*3456 + mt_c*576;
    int kk0 = gid*14;
    int barid = gid + 1;
    int s8 = (tig & 2) << 2;   // V col swizzle for this lane's rows

    int bh_prev = -1;
    float maxknorm = 0.f;
    const float* gq = nullptr;
    int b = 0, h = 0;

    for (int uu = 0; uu < cnt; uu++) {
        int u  = ustart + uu;
        int bh = u / 28;
        int i  = u - bh*28;

        if (bh != bh_prev) {
            bh_prev = bh;
            b = bh >> 3; h = bh & 7;
            gq = d_q + (size_t)bh*NPOS*MID;
            __syncthreads();           // all reads of old K/V done (first iter: trivial)
            if (t == 0) *ctrl = 0;

            const float4* gk4 = (const float4*)(d_k + (size_t)bh*NPOS*MID);
            const float4* gv4 = (const float4*)(d_v + (size_t)bh*NPOS*MID);
            for (int idx = t; idx < 3136; idx += 512) {
                int mg = idx & 3, pos = idx >> 2;
                int kk = pos / 28, ll = pos - kk*28;
                float4 kv = gk4[idx];
                float* kb = Ksh + (kk*16 + mg*4)*33 + ll;
                kb[0] = kv.x; kb[33] = kv.y; kb[66] = kv.z; kb[99] = kv.w;
                float4 vv = gv4[idx];
                vv.x = __uint_as_float(tf32_(vv.x));
                vv.y = __uint_as_float(tf32_(vv.y));
                vv.z = __uint_as_float(tf32_(vv.z));
                vv.w = __uint_as_float(tf32_(vv.w));
                int sw = ((ll >> 1) & 1) << 1;
                ((float4*)(Vsh + (kk*32 + ll)*16))[mg ^ sw] = vv;
            }
            __syncthreads();

            // max ||k||^2
            float mx = 0.f;
            for (int pos = t; pos < NPOS; pos += 512) {
                int kk = pos / 28, ll = pos - kk*28;
                float n2 = 0.f;
#pragma unroll
                for (int cc = 0; cc < 16; cc++) { float kv = Ksh[(kk*16+cc)*33 + ll]; n2 += kv*kv; }
                mx = fmaxf(mx, n2);
            }
#pragma unroll
            for (int off = 16; off; off >>= 1) mx = fmaxf(mx, __shfl_xor_sync(~0u, mx, off));
            if (lane == 0) atomicMax(ctrl, __float_as_int(mx));
            __syncthreads();
            maxknorm = sqrtf(__int_as_float(*ctrl));
        }

        // ---- per-i: load Q (scaled to log2 domain) ----
        {
            int row = t >> 4, ch = t & 15;
            Qs[t & 511] = (row < 28) ? gq[(size_t)(i*28 + row)*16 + ch] * QLOG2 : 0.f;
        }
        __syncthreads();

        // per-row tables fR/fC (from smem-cached embeddings)
        for (int idx = t; idx < 32*110; idx += 512) {
            int j = idx / 110, a = idx - j*110;
            const float4* er = (const float4*)(Ersh + a*8);
            const float4* ec = (const float4*)(Ecsh + a*8);
            float4 e0 = er[0], e1 = er[1], c0 = ec[0], c1 = ec[1];
            const float* q = Qs + j*16;
            float fr = q[0]*e0.x + q[1]*e0.y + q[2]*e0.z + q[3]*e0.w
                     + q[4]*e1.x + q[5]*e1.y + q[6]*e1.z + q[7]*e1.w;
            float fc = q[8]*c0.x + q[9]*c0.y + q[10]*c0.z + q[11]*c0.w
                     + q[12]*c1.x + q[13]*c1.y + q[14]*c1.z + q[15]*c1.w;
            fRs[j*112 + a] = fr;
            fCs[j*112 + a] = fc;
        }
        __syncthreads();
        // parallel nM
        {
            int j = t >> 4, s = t & 15;
            float q = Qs[j*16 + s];
            float qn = q*q;
            float mR = -1e30f, mC = -1e30f;
            for (int a = s; a < NREL; a += 16) {
                mR = fmaxf(mR, fRs[j*112 + a]);
                mC = fmaxf(mC, fCs[j*112 + a]);
            }
#pragma unroll
            for (int off = 8; off; off >>= 1) {
                qn += __shfl_xor_sync(~0u, qn, off);
                mR = fmaxf(mR, __shfl_xor_sync(~0u, mR, off));
                mC = fmaxf(mC, __shfl_xor_sync(~0u, mC, off));
            }
            if (s == 0) nM[j] = -(sqrtf(qn)*maxknorm + mR + mC + 0.25f);
        }
        __syncthreads();

        // ---- producer frags ----
        uint qhi[2][4], qlo[2][4];
#pragma unroll
        for (int kc = 0; kc < 2; kc++) {
#pragma unroll
            for (int e = 0; e < 4; e++) {
                int r = grp + (e & 1)*8;
                int cc = kc*8 + tig + (e >> 1)*4;
                float f = Qs[(mt_p*16 + r)*16 + cc];
                uint hi = tf32_(f);
                qhi[kc][e] = hi;
                qlo[kc][e] = tf32_(f - __uint_as_float(hi));
            }
        }

        // ---- consumer constants ----
        float nm0 = nM[j0], nm1 = nM[j1];
        float tpr[4][4];
#pragma unroll
        for (int ch = 0; ch < 4; ch++) {
#pragma unroll
            for (int e = 0; e < 4; e++) {
                int j  = (e & 1) ? j1 : j0;
                int ll = ch*8 + tig + (e >> 1)*4;
                float tv;
                if (ll >= 28) tv = -1e30f;
                else {
                    int C = ll - j + 27;
                    C = max(0, min(54, C));
                    float v;
                    if      (g_c == 0) v = fCs[j*112 + C];
                    else if (g_c == 1) v = fRs[j*112 + C + 55];
                    else if (g_c == 2) v = fCs[j*112 + C + 55];
                    else               v = fRs[j*112 + C];
                    tv = v + ((e & 1) ? nm1 : nm0);
                }
                tpr[ch][e] = tv;
            }
        }

        float o0_0=0,o0_1=0,o0_2=0,o0_3=0;
        float o1_0=0,o1_1=0,o1_2=0,o1_3=0;
        float su0 = 0.f, su1 = 0.f;

        auto produceS = [&](int kk, int buf) {
            float s0=0.f, s1=0.f, s2=0.f, s3=0.f;
#pragma unroll
            for (int kc = 0; kc < 2; kc++) {
                const float* kp = Ksh + (kk*16 + kc*8 + tig)*33 + nt_p*8 + grp;
                float f0 = kp[0], f1 = kp[4*33];
                uint bh0 = tf32_(f0), bh1 = tf32_(f1);
                uint bl0 = tf32_(f0 - __uint_as_float(bh0));
                uint bl1 = tf32_(f1 - __uint_as_float(bh1));
                MMA_TF32(s0,s1,s2,s3, qhi[kc][0],qhi[kc][1],qhi[kc][2],qhi[kc][3], bh0,bh1);
                MMA_TF32(s0,s1,s2,s3, qhi[kc][0],qhi[kc][1],qhi[kc][2],qhi[kc][3], bl0,bl1);
                MMA_TF32(s0,s1,s2,s3, qlo[kc][0],qlo[kc][1],qlo[kc][2],qlo[kc][3], bh0,bh1);
            }
            float* sp = Sb + sbase_p + buf*1152;
            *(float2*)(sp + grp*36 + 2*tig)     = make_float2(s0, s1);
            *(float2*)(sp + (grp+8)*36 + 2*tig) = make_float2(s2, s3);
        };

        auto consumeS = [&](int kk, int buf) {
            int sidx = kk - i + 27 + soff;
            float sj0 = stab[j0*112 + sidx];
            float sj1 = stab[j1*112 + sidx];
            const float* sc = Sb + sbase_c + buf*1152;
            const float* vb = Vsh + kk*512;
#pragma unroll
            for (int ch = 0; ch < 4; ch++) {
                float l0 = sc[grp*36     + ch*8 + tig];
                float l1 = sc[(grp+8)*36 + ch*8 + tig];
                float l2 = sc[grp*36     + ch*8 + tig + 4];
                float l3 = sc[(grp+8)*36 + ch*8 + tig + 4];
                float e0 = ex2_(l0 + sj0 + tpr[ch][0]);
                float e1 = ex2_(l1 + sj1 + tpr[ch][1]);
                float e2 = ex2_(l2 + sj0 + tpr[ch][2]);
                float e3 = ex2_(l3 + sj1 + tpr[ch][3]);
                uint p0 = tf32_(e0), p1 = tf32_(e1), p2 = tf32_(e2), p3 = tf32_(e3);
                su0 += __uint_as_float(p0) + __uint_as_float(p2);
                su1 += __uint_as_float(p1) + __uint_as_float(p3);
                const float* vp = vb + (ch*8 + tig)*16;
                uint v00 = __float_as_uint(vp[grp ^ s8]);
                uint v10 = __float_as_uint(vp[(grp+8) ^ s8]);
                uint v01 = __float_as_uint(vp[64 + (grp ^ s8)]);
                uint v11 = __float_as_uint(vp[64 + ((grp+8) ^ s8)]);
                MMA_TF32(o0_0,o0_1,o0_2,o0_3, p0,p1,p2,p3, v00,v01);
                MMA_TF32(o1_0,o1_1,o1_2,o1_3, p0,p1,p2,p3, v10,v11);
            }
        };

        // skew-2 pipeline
        produceS(kk0 + 0, 0);
        produceS(kk0 + 1, 1);
        asm volatile("bar.sync %0, 256;" :: "r"(barid) : "memory");
        int bufp = 2, bufc = 0;
#pragma unroll 2
        for (int kx = 0; kx < 14; kx++) {
            if (kx < 12) produceS(kk0 + kx + 2, bufp);
            consumeS(kk0 + kx, bufc);
            if (++bufp == 3) bufp = 0;
            if (++bufc == 3) bufc = 0;
            asm volatile("bar.sync %0, 256;" :: "r"(barid) : "memory");
        }

        // ---- row sums within group ----
        su0 += __shfl_xor_sync(~0u, su0, 1); su0 += __shfl_xor_sync(~0u, su0, 2);
        su1 += __shfl_xor_sync(~0u, su1, 1); su1 += __shfl_xor_sync(~0u, su1, 2);

        // ---- combine groups ----
        __syncthreads();
        if (gid == 1) {
            float* e = EX + (wl*32 + lane)*10;
            e[0]=o0_0; e[1]=o0_1; e[2]=o0_2; e[3]=o0_3;
            e[4]=o1_0; e[5]=o1_1; e[6]=o1_2; e[7]=o1_3;
            e[8]=su0;  e[9]=su1;
        }
        __syncthreads();
        if (gid == 0) {
            const float* e = EX + (wl*32 + lane)*10;
            o0_0+=e[0]; o0_1+=e[1]; o0_2+=e[2]; o0_3+=e[3];
            o1_0+=e[4]; o1_1+=e[5]; o1_2+=e[6]; o1_3+=e[7];
            su0 +=e[8]; su1 +=e[9];

            float inv0, inv1;
            asm("rcp.approx.f32 %0,%1;" : "=f"(inv0) : "f"(su0));
            asm("rcp.approx.f32 %0,%1;" : "=f"(inv1) : "f"(su1));

            size_t obase = ((size_t)(b*G + g_c)*NPOS + i*28)*128 + h;
            {
                size_t rb = obase + (size_t)j0*128;
                int m0 = 2*tig;
                d_outv[rb + (m0  )*8] = o0_0*inv0;
                d_outv[rb + (m0+1)*8] = o0_1*inv0;
                d_outv[rb + (m0+8)*8] = o1_0*inv0;
                d_outv[rb + (m0+9)*8] = o1_1*inv0;
            }
            if (j1 < 28) {
                size_t rb = obase + (size_t)j1*128;
                int m0 = 2*tig;
                d_outv[rb + (m0  )*8] = o0_2*inv1;
                d_outv[rb + (m0+1)*8] = o0_3*inv1;
                d_outv[rb + (m0+8)*8] = o1_2*inv1;
                d_outv[rb + (m0+9)*8] = o1_3*inv1;
            }
        }
        __syncthreads();   // protect Qs/tables before next unit
    }
}

// ---------------- output 1x1 conv, FFMA2 tiled SGEMM (64x64, 196 blocks) ----------------
#define OPAD 68
#define OUT_SMEM_BYTES (2*128*OPAD*4)
__global__ void __launch_bounds__(256, 2) out_gemm(const float* __restrict__ wout,
                                                   const float* __restrict__ bout,
                                                   float* __restrict__ out)
{
    extern __shared__ float osh[];
    float* Xs = osh;               // [k][r], stride OPAD
    float* Ws = osh + 128*OPAD;    // [k][c], stride OPAD

    int t = threadIdx.x;
    int Rbase = blockIdx.x * 64;

    for (int idx = t; idx < 2048; idx += 256) {
        int r = idx & 63, c4 = idx >> 6;
        float4 val = ((const float4*)d_outv)[(size_t)(Rbase + r)*32 + c4];
        Xs[(4*c4+0)*OPAD + r] = val.x;
        Xs[(4*c4+1)*OPAD + r] = val.y;
        Xs[(4*c4+2)*OPAD + r] = val.z;
        Xs[(4*c4+3)*OPAD + r] = val.w;
    }
    for (int idx = t; idx < 2048; idx += 256) {
        int o = idx & 63, c4 = idx >> 6;
        float4 val = ((const float4*)wout)[o*32 + c4];
        Ws[(4*c4+0)*OPAD + o] = val.x;
        Ws[(4*c4+1)*OPAD + o] = val.y;
        Ws[(4*c4+2)*OPAD + o] = val.z;
        Ws[(4*c4+3)*OPAD + o] = val.w;
    }
    __syncthreads();

    int tx = t & 15, ty = t >> 4;
    ull a0c01=0, a0c23=0, a1c01=0, a1c23=0, a2c01=0, a2c23=0, a3c01=0, a3c23=0;

#pragma unroll 8
    for (int k = 0; k < 128; k++) {
        float4 av = *(const float4*)&Xs[k*OPAD + 4*tx];
        ulonglong2 bv = *(const ulonglong2*)&Ws[k*OPAD + 4*ty];
        ull ab0 = pk2(av.x, av.x), ab1 = pk2(av.y, av.y);
        ull ab2 = pk2(av.z, av.z), ab3 = pk2(av.w, av.w);
        a0c01 = fma2_(ab0, bv.x, a0c01);  a0c23 = fma2_(ab0, bv.y, a0c23);
        a1c01 = fma2_(ab1, bv.x, a1c01);  a1c23 = fma2_(ab1, bv.y, a1c23);
        a2c01 = fma2_(ab2, bv.x, a2c01);  a2c23 = fma2_(ab2, bv.y, a2c23);
        a3c01 = fma2_(ab3, bv.x, a3c01);  a3c23 = fma2_(ab3, bv.y, a3c23);
    }

    float vals[4][4];
    upk2(a0c01, vals[0][0], vals[0][1]);  upk2(a0c23, vals[0][2], vals[0][3]);
    upk2(a1c01, vals[1][0], vals[1][1]);  upk2(a1c23, vals[1][2], vals[1][3]);
    upk2(a2c01, vals[2][0], vals[2][1]);  upk2(a2c23, vals[2][2], vals[2][3]);
    upk2(a3c01, vals[3][0], vals[3][1]);  upk2(a3c23, vals[3][2], vals[3][3]);

    int R0 = Rbase + 4*tx;
    int bb = R0 / (G*NPOS);
    int rem = R0 - bb*(G*NPOS);
    int g = rem / NPOS;
    int pos = rem - g*NPOS;

#pragma unroll
    for (int ci = 0; ci < 4; ci++) {
        int o = 4*ty + ci;
        float bi = bout[o];
        float4 v = make_float4(vals[0][ci] + bi, vals[1][ci] + bi,
                               vals[2][ci] + bi, vals[3][ci] + bi);
        *(float4*)&out[(((size_t)(bb*COUT + o))*G + g)*NPOS + pos] = v;
    }
}

// ---------------- launch ----------------
extern "C" void kernel_launch(void* const* d_in, const int* in_sizes, int n_in,
                              void* d_out, int out_size)
{
    const float* x     = (const float*)d_in[0];
    const float* wq    = (const float*)d_in[1];
    const float* bq    = (const float*)d_in[2];
    const float* wk    = (const float*)d_in[3];
    const float* bk    = (const float*)d_in[4];
    const float* wv    = (const float*)d_in[5];
    const float* bv    = (const float*)d_in[6];
    const float* w_out = (const float*)d_in[7];
    const float* b_out = (const float*)d_in[8];
    const float* row_w1 = (const float*)d_in[9];
    const float* row_b1 = (const float*)d_in[10];
    const float* row_g  = (const float*)d_in[11];
    const float* row_be = (const float*)d_in[12];
    const float* row_w2 = (const float*)d_in[13];
    const float* row_b2 = (const float*)d_in[14];
    const float* col_w1 = (const float*)d_in[15];
    const float* col_b1 = (const float*)d_in[16];
    const float* col_g  = (const float*)d_in[17];
    const float* col_be = (const float*)d_in[18];
    const float* col_w2 = (const float*)d_in[19];
    const float* col_b2 = (const float*)d_in[20];

    cudaFuncSetAttribute(attn_kernel, cudaFuncAttributeMaxDynamicSharedMemorySize, ATTN_SMEM_BYTES);
    cudaFuncSetAttribute(out_gemm,    cudaFuncAttributeMaxDynamicSharedMemorySize, OUT_SMEM_BYTES);

    qkv_embed_kernel<<<393, 256>>>(x, wq, bq, wk, bk, wv, bv,
                                   row_w1, row_b1, row_g, row_be, row_w2, row_b2,
                                   col_w1, col_b1, col_g, col_be, col_w2, col_b2);

    attn_kernel<<<148, 512, ATTN_SMEM_BYTES>>>();

    out_gemm<<<196, 256, OUT_SMEM_BYTES>>>(w_out, b_out, (float*)d_out);
}

// round 17
// speedup vs baseline: 1.1142x; 1.0446x over previous
#include <cuda_runtime.h>

#define BATCH 4
#define HEADS 8
#define MID 16
#define G 4
#define COUT 64
#define WDIM 28
#define NPOS 784
#define NREL 110
#define QLOG2 0.8329091229351039f   // (1/sqrt(3)) * log2(e)

typedef unsigned long long ull;
typedef unsigned int uint;

__device__ __forceinline__ float ex2_(float x){ float r; asm("ex2.approx.f32 %0,%1;":"=f"(r):"f"(x)); return r; }
__device__ __forceinline__ uint tf32_(float f){ uint u; asm("cvt.rna.tf32.f32 %0,%1;":"=r"(u):"f"(f)); return u; }
__device__ __forceinline__ ull pk2(float lo, float hi){ ull r; asm("mov.b64 %0,{%1,%2};":"=l"(r):"f"(lo),"f"(hi)); return r; }
__device__ __forceinline__ void upk2(ull v, float& lo, float& hi){ asm("mov.b64 {%0,%1},%2;":"=f"(lo),"=f"(hi):"l"(v)); }
__device__ __forceinline__ ull fma2_(ull a, ull b, ull c){ ull d; asm("fma.rn.f32x2 %0,%1,%2,%3;":"=l"(d):"l"(a),"l"(b),"l"(c)); return d; }

#define MMA_TF32(d0,d1,d2,d3,a0,a1,a2,a3,b0,b1) \
    asm volatile("mma.sync.aligned.m16n8k8.row.col.f32.tf32.tf32.f32 " \
        "{%0,%1,%2,%3},{%4,%5,%6,%7},{%8,%9},{%0,%1,%2,%3};" \
        : "+f"(d0),"+f"(d1),"+f"(d2),"+f"(d3) \
        : "r"(a0),"r"(a1),"r"(a2),"r"(a3),"r"(b0),"r"(b1))

// ---------------- device scratch ----------------
__device__ float d_q[BATCH*HEADS*NPOS*MID];   // [bh][pos][16]
__device__ float d_k[BATCH*HEADS*NPOS*MID];
__device__ float d_v[BATCH*HEADS*NPOS*MID];
__device__ float d_Er[NREL*8];
__device__ float d_Ec[NREL*8];
__device__ float d_outv[BATCH*G*NPOS*(MID*HEADS)];   // [b][g][pos][m*8+h]

// ---------------- fused q/k/v conv + embedding MLP (extra block) ----------------
__global__ void qkv_embed_kernel(
    const float* __restrict__ x,
    const float* __restrict__ wq, const float* __restrict__ bq,
    const float* __restrict__ wk, const float* __restrict__ bk,
    const float* __restrict__ wv, const float* __restrict__ bv,
    const float* __restrict__ w1r, const float* __restrict__ b1r,
    const float* __restrict__ gr,  const float* __restrict__ ber,
    const float* __restrict__ w2r, const float* __restrict__ b2r,
    const float* __restrict__ w1c, const float* __restrict__ b1c,
    const float* __restrict__ gc,  const float* __restrict__ bec,
    const float* __restrict__ w2c, const float* __restrict__ b2c)
{
    if (blockIdx.x == 392) {
        // ---- embedding MLP: 220 rows ----
        int t = threadIdx.x;
        if (t >= 2*NREL) return;
        bool isRow = (t < NREL);
        int a = isRow ? t : t - NREL;
        const float* w1 = isRow ? w1r : w1c;
        const float* b1 = isRow ? b1r : b1c;
        const float* ga = isRow ? gr  : gc;
        const float* be = isRow ? ber : bec;
        const float* w2 = isRow ? w2r : w2c;
        const float* b2 = isRow ? b2r : b2c;

        float u;
        if (a < 55) u = a * (2.0f/54.0f) - 1.0f;
        else        u = -((a-55) * (2.0f/54.0f) - 1.0f);

        float h[16];
        float mu = 0.f;
#pragma unroll
        for (int c = 0; c < 16; c++) { h[c] = u*w1[c] + b1[c]; mu += h[c]; }
        mu *= (1.0f/16.0f);
        float var = 0.f;
#pragma unroll
        for (int c = 0; c < 16; c++) { float d = h[c]-mu; var += d*d; }
        var *= (1.0f/16.0f);
        float inv = rsqrtf(var + 1e-5f);
#pragma unroll
        for (int c = 0; c < 16; c++) {
            float hn = ga[c]*(h[c]-mu)*inv + be[c];
            h[c] = hn / (1.0f + expf(-hn));
        }
        float* out = isRow ? d_Er : d_Ec;
#pragma unroll
        for (int d = 0; d < 8; d++) {
            float s = b2[d];
#pragma unroll
            for (int c = 0; c < 16; c++) s += h[c]*w2[d*16+c];
            out[a*8 + d] = s;
        }
        return;
    }

    // ---- q/k/v 1x1 conv ----
    int idx = blockIdx.x*blockDim.x + threadIdx.x;
    if (idx >= BATCH*HEADS*NPOS*4) return;
    int mg  = idx & 3;
    int r   = idx >> 2;
    int pos = r % NPOS;
    int r2  = r / NPOS;
    int h   = r2 & 7;
    int b   = r2 >> 3;

    float x0 = x[(b*3+0)*NPOS + pos];
    float x1 = x[(b*3+1)*NPOS + pos];
    float x2 = x[(b*3+2)*NPOS + pos];

    float4 qv, kv, vv;
    float* qp = (float*)&qv; float* kp = (float*)&kv; float* vp = (float*)&vv;
#pragma unroll
    for (int mi = 0; mi < 4; mi++) {
        int o = (mg*4 + mi)*8 + h;
        qp[mi] = bq[o] + wq[o*3+0]*x0 + wq[o*3+1]*x1 + wq[o*3+2]*x2;
        kp[mi] = bk[o] + wk[o*3+0]*x0 + wk[o*3+1]*x1 + wk[o*3+2]*x2;
        vp[mi] = bv[o] + wv[o*3+0]*x0 + wv[o*3+1]*x1 + wv[o*3+2]*x2;
    }
    size_t dst4 = ((size_t)(b*HEADS + h)*NPOS + pos)*4 + mg;
    ((float4*)d_q)[dst4] = qv;
    ((float4*)d_k)[dst4] = kv;
    ((float4*)d_v)[dst4] = vv;
}

// ---------------- tf32 TC attention: CTA = (bh, i-pair), 2 kk-groups, skew-2 ----------------
// (identical to Round-14 kernel — best measured config)
#define SM_K    0            // [28][16][33] = 14784
#define SM_V    14784        // [28][32][16] = 14336 (tf32 bits, col-swizzled)
#define SM_S    29120        // [2 groups][3 bufs][32][36] = 6912
#define SM_FR   36032        // [32][112]
#define SM_FC   39616        // [32][112]
#define SM_Q    43200        // [32][16]
#define SM_NM   43712        // [32]
#define SM_EX   43744        // [8 warps][32 lanes][10] = 2560
#define SM_CTRL 46304
#define SM_ER   46308        // [110][8] = 880
#define SM_EC   47188        // [110][8] = 880
#define SM_TOT  48068
#define ATTN_SMEM_BYTES (SM_TOT*4)

__global__ void __launch_bounds__(512, 1) attn_kernel()
{
    extern __shared__ float sm[];
    float* Ksh  = sm + SM_K;
    float* Vsh  = sm + SM_V;
    float* Sb   = sm + SM_S;
    float* fRs  = sm + SM_FR;
    float* fCs  = sm + SM_FC;
    float* Qs   = sm + SM_Q;
    float* nM   = sm + SM_NM;
    float* EX   = sm + SM_EX;
    float* Ersh = sm + SM_ER;
    float* Ecsh = sm + SM_EC;
    int*  ctrl  = (int*)(sm + SM_CTRL);

    int t = threadIdx.x;
    int w = t >> 5, lane = t & 31, grp = lane >> 2, tig = lane & 3;
    int gid = w >> 3;          // kk-group
    int wl  = w & 7;
    int bx = blockIdx.x;
    int i0 = (bx % 14) * 2;    // i-pair {i0, i0+1}
    int bh = bx / 14;
    int b  = bh >> 3, h = bh & 7;

    if (t == 0) *ctrl = 0;

    const float4* gk4 = (const float4*)(d_k + (size_t)bh*NPOS*MID);
    const float4* gv4 = (const float4*)(d_v + (size_t)bh*NPOS*MID);
    const float*  gq  = d_q + (size_t)bh*NPOS*MID;

    // cache Er/Ec in smem (once per CTA)
    if (t < 220) {
        ((float4*)Ersh)[t] = ((const float4*)d_Er)[t];
        ((float4*)Ecsh)[t] = ((const float4*)d_Ec)[t];
    }

    // targeted padding zero: K cols 28..32 of each 33-wide row; V rows ll 28..31
    for (int idx = t; idx < 2240; idx += 512) {
        int row = idx / 5, c = idx - row*5;
        Ksh[row*33 + 28 + c] = 0.f;
    }
    for (int idx = t; idx < 1792; idx += 512) {
        int kk = idx >> 6, r = idx & 63;
        Vsh[(kk*32 + 28)*16 + r] = 0.f;
    }

    for (int idx = t; idx < 3136; idx += 512) {
        int mg = idx & 3, pos = idx >> 2;
        int kk = pos / 28, ll = pos - kk*28;
        float4 kv = gk4[idx];
        float* kb = Ksh + (kk*16 + mg*4)*33 + ll;
        kb[0] = kv.x; kb[33] = kv.y; kb[66] = kv.z; kb[99] = kv.w;
        float4 vv = gv4[idx];
        vv.x = __uint_as_float(tf32_(vv.x));
        vv.y = __uint_as_float(tf32_(vv.y));
        vv.z = __uint_as_float(tf32_(vv.z));
        vv.w = __uint_as_float(tf32_(vv.w));
        int sw = ((ll >> 1) & 1) << 1;
        ((float4*)(Vsh + (kk*32 + ll)*16))[mg ^ sw] = vv;
    }
    __syncthreads();

    // max ||k||^2 (once per bh)
    {
        float mx = 0.f;
        for (int pos = t; pos < NPOS; pos += 512) {
            int kk = pos / 28, ll = pos - kk*28;
            float n2 = 0.f;
#pragma unroll
            for (int c = 0; c < 16; c++) { float kv = Ksh[(kk*16+c)*33 + ll]; n2 += kv*kv; }
            mx = fmaxf(mx, n2);
        }
#pragma unroll
        for (int off = 16; off; off >>= 1) mx = fmaxf(mx, __shfl_xor_sync(~0u, mx, off));
        if (lane == 0) atomicMax(ctrl, __float_as_int(mx));
    }
    __syncthreads();
    float maxknorm = sqrtf(__int_as_float(*ctrl));

    // role constants (i-independent)
    int mt_p = wl >> 2, nt_p = wl & 3;
    int g_c = wl >> 1, mt_c = wl & 1;
    const float* stab = (g_c == 0 || g_c == 2) ? fRs : fCs;
    int soff = (g_c >= 2) ? 55 : 0;
    int j0 = mt_c*16 + grp, j1 = j0 + 8;
    int sbase_p = gid*3456 + mt_p*576 + nt_p*8;
    int sbase_c = gid*3456 + mt_c*576;
    int kk0 = gid*14;
    int barid = gid + 1;
    int s8 = (tig & 2) << 2;   // V col swizzle for this lane's rows

    for (int ii = 0; ii < 2; ii++) {
        int i = i0 + ii;

        // ---- per-i: load Q (scaled to log2 domain) ----
        {
            int row = t >> 4, ch = t & 15;
            Qs[t & 511] = (row < 28) ? gq[(size_t)(i*28 + row)*16 + ch] * QLOG2 : 0.f;
        }
        __syncthreads();

        // per-row tables fR/fC (from smem-cached embeddings)
        for (int idx = t; idx < 32*110; idx += 512) {
            int j = idx / 110, a = idx - j*110;
            const float4* er = (const float4*)(Ersh + a*8);
            const float4* ec = (const float4*)(Ecsh + a*8);
            float4 e0 = er[0], e1 = er[1], c0 = ec[0], c1 = ec[1];
            const float* q = Qs + j*16;
            float fr = q[0]*e0.x + q[1]*e0.y + q[2]*e0.z + q[3]*e0.w
                     + q[4]*e1.x + q[5]*e1.y + q[6]*e1.z + q[7]*e1.w;
            float fc = q[8]*c0.x + q[9]*c0.y + q[10]*c0.z + q[11]*c0.w
                     + q[12]*c1.x + q[13]*c1.y + q[14]*c1.z + q[15]*c1.w;
            fRs[j*112 + a] = fr;
            fCs[j*112 + a] = fc;
        }
        __syncthreads();
        // parallel nM: thread (j = t>>4, s = t&15)
        {
            int j = t >> 4, s = t & 15;
            float q = Qs[j*16 + s];
            float qn = q*q;
            float mR = -1e30f, mC = -1e30f;
            for (int a = s; a < NREL; a += 16) {
                mR = fmaxf(mR, fRs[j*112 + a]);
                mC = fmaxf(mC, fCs[j*112 + a]);
            }
#pragma unroll
            for (int off = 8; off; off >>= 1) {
                qn += __shfl_xor_sync(~0u, qn, off);
                mR = fmaxf(mR, __shfl_xor_sync(~0u, mR, off));
                mC = fmaxf(mC, __shfl_xor_sync(~0u, mC, off));
            }
            if (s == 0) nM[j] = -(sqrtf(qn)*maxknorm + mR + mC + 0.25f);
        }
        __syncthreads();

        // ---- producer frags ----
        uint qhi[2][4], qlo[2][4];
#pragma unroll
        for (int kc = 0; kc < 2; kc++) {
#pragma unroll
            for (int e = 0; e < 4; e++) {
                int r = grp + (e & 1)*8;
                int c = kc*8 + tig + (e >> 1)*4;
                float f = Qs[(mt_p*16 + r)*16 + c];
                uint hi = tf32_(f);
                qhi[kc][e] = hi;
                qlo[kc][e] = tf32_(f - __uint_as_float(hi));
            }
        }

        // ---- consumer constants ----
        float nm0 = nM[j0], nm1 = nM[j1];
        float tpr[4][4];
#pragma unroll
        for (int ch = 0; ch < 4; ch++) {
#pragma unroll
            for (int e = 0; e < 4; e++) {
                int j  = (e & 1) ? j1 : j0;
                int ll = ch*8 + tig + (e >> 1)*4;
                float tv;
                if (ll >= 28) tv = -1e30f;
                else {
                    int C = ll - j + 27;
                    C = max(0, min(54, C));
                    float v;
                    if      (g_c == 0) v = fCs[j*112 + C];
                    else if (g_c == 1) v = fRs[j*112 + C + 55];
                    else if (g_c == 2) v = fCs[j*112 + C + 55];
                    else               v = fRs[j*112 + C];
                    tv = v + ((e & 1) ? nm1 : nm0);
                }
                tpr[ch][e] = tv;
            }
        }

        float o0_0=0,o0_1=0,o0_2=0,o0_3=0;
        float o1_0=0,o1_1=0,o1_2=0,o1_3=0;
        float su0 = 0.f, su1 = 0.f;

        auto produceS = [&](int kk, int buf) {
            float s0=0.f, s1=0.f, s2=0.f, s3=0.f;
#pragma unroll
            for (int kc = 0; kc < 2; kc++) {
                const float* kp = Ksh + (kk*16 + kc*8 + tig)*33 + nt_p*8 + grp;
                float f0 = kp[0], f1 = kp[4*33];
                uint bh0 = tf32_(f0), bh1 = tf32_(f1);
                uint bl0 = tf32_(f0 - __uint_as_float(bh0));
                uint bl1 = tf32_(f1 - __uint_as_float(bh1));
                MMA_TF32(s0,s1,s2,s3, qhi[kc][0],qhi[kc][1],qhi[kc][2],qhi[kc][3], bh0,bh1);
                MMA_TF32(s0,s1,s2,s3, qhi[kc][0],qhi[kc][1],qhi[kc][2],qhi[kc][3], bl0,bl1);
                MMA_TF32(s0,s1,s2,s3, qlo[kc][0],qlo[kc][1],qlo[kc][2],qlo[kc][3], bh0,bh1);
            }
            float* sp = Sb + sbase_p + buf*1152;
            *(float2*)(sp + grp*36 + 2*tig)     = make_float2(s0, s1);
            *(float2*)(sp + (grp+8)*36 + 2*tig) = make_float2(s2, s3);
        };

        auto consumeS = [&](int kk, int buf) {
            int sidx = kk - i + 27 + soff;
            float sj0 = stab[j0*112 + sidx];
            float sj1 = stab[j1*112 + sidx];
            const float* sc = Sb + sbase_c + buf*1152;
            const float* vb = Vsh + kk*512;
#pragma unroll
            for (int ch = 0; ch < 4; ch++) {
                float l0 = sc[grp*36     + ch*8 + tig];
                float l1 = sc[(grp+8)*36 + ch*8 + tig];
                float l2 = sc[grp*36     + ch*8 + tig + 4];
                float l3 = sc[(grp+8)*36 + ch*8 + tig + 4];
                float e0 = ex2_(l0 + sj0 + tpr[ch][0]);
                float e1 = ex2_(l1 + sj1 + tpr[ch][1]);
                float e2 = ex2_(l2 + sj0 + tpr[ch][2]);
                float e3 = ex2_(l3 + sj1 + tpr[ch][3]);
                uint p0 = tf32_(e0), p1 = tf32_(e1), p2 = tf32_(e2), p3 = tf32_(e3);
                su0 += __uint_as_float(p0) + __uint_as_float(p2);
                su1 += __uint_as_float(p1) + __uint_as_float(p3);
                const float* vp = vb + (ch*8 + tig)*16;
                uint v00 = __float_as_uint(vp[grp ^ s8]);
                uint v10 = __float_as_uint(vp[(grp+8) ^ s8]);
                uint v01 = __float_as_uint(vp[64 + (grp ^ s8)]);
                uint v11 = __float_as_uint(vp[64 + ((grp+8) ^ s8)]);
                MMA_TF32(o0_0,o0_1,o0_2,o0_3, p0,p1,p2,p3, v00,v01);
                MMA_TF32(o1_0,o1_1,o1_2,o1_3, p0,p1,p2,p3, v10,v11);
            }
        };

        // skew-2 pipeline
        produceS(kk0 + 0, 0);
        produceS(kk0 + 1, 1);
        asm volatile("bar.sync %0, 256;" :: "r"(barid) : "memory");
        int bufp = 2, bufc = 0;
#pragma unroll 2
        for (int kx = 0; kx < 14; kx++) {
            if (kx < 12) produceS(kk0 + kx + 2, bufp);
            consumeS(kk0 + kx, bufc);
            if (++bufp == 3) bufp = 0;
            if (++bufc == 3) bufc = 0;
            asm volatile("bar.sync %0, 256;" :: "r"(barid) : "memory");
        }

        // ---- row sums within group ----
        su0 += __shfl_xor_sync(~0u, su0, 1); su0 += __shfl_xor_sync(~0u, su0, 2);
        su1 += __shfl_xor_sync(~0u, su1, 1); su1 += __shfl_xor_sync(~0u, su1, 2);

        // ---- combine groups ----
        __syncthreads();
        if (gid == 1) {
            float* e = EX + (wl*32 + lane)*10;
            e[0]=o0_0; e[1]=o0_1; e[2]=o0_2; e[3]=o0_3;
            e[4]=o1_0; e[5]=o1_1; e[6]=o1_2; e[7]=o1_3;
            e[8]=su0;  e[9]=su1;
        }
        __syncthreads();
        if (gid == 0) {
            const float* e = EX + (wl*32 + lane)*10;
            o0_0+=e[0]; o0_1+=e[1]; o0_2+=e[2]; o0_3+=e[3];
            o1_0+=e[4]; o1_1+=e[5]; o1_2+=e[6]; o1_3+=e[7];
            su0 +=e[8]; su1 +=e[9];

            float inv0, inv1;
            asm("rcp.approx.f32 %0,%1;" : "=f"(inv0) : "f"(su0));
            asm("rcp.approx.f32 %0,%1;" : "=f"(inv1) : "f"(su1));

            size_t obase = ((size_t)(b*G + g_c)*NPOS + i*28)*128 + h;
            {
                size_t rb = obase + (size_t)j0*128;
                int m0 = 2*tig;
                d_outv[rb + (m0  )*8] = o0_0*inv0;
                d_outv[rb + (m0+1)*8] = o0_1*inv0;
                d_outv[rb + (m0+8)*8] = o1_0*inv0;
                d_outv[rb + (m0+9)*8] = o1_1*inv0;
            }
            if (j1 < 28) {
                size_t rb = obase + (size_t)j1*128;
                int m0 = 2*tig;
                d_outv[rb + (m0  )*8] = o0_2*inv1;
                d_outv[rb + (m0+1)*8] = o0_3*inv1;
                d_outv[rb + (m0+8)*8] = o1_2*inv1;
                d_outv[rb + (m0+9)*8] = o1_3*inv1;
            }
        }
        __syncthreads();   // protect Qs/tables before next ii
    }
}

// ---------------- output 1x1 conv: split-tf32 tensor-core GEMM ----------------
// C[12544, 64] = X[12544, 128] @ W^T, 98 CTAs x 128 rows, single wave.
#define OG_PX 132
#define OG_XH 0                       // Xhi [128][132]
#define OG_XL (128*OG_PX)             // Xlo [128][132]
#define OG_WH (2*128*OG_PX)           // Whi [64][132]
#define OG_WL (2*128*OG_PX + 64*OG_PX)
#define OG_TOT (2*128*OG_PX + 2*64*OG_PX)
#define OUT_SMEM_BYTES (OG_TOT*4)

__global__ void __launch_bounds__(256, 1) out_gemm(const float* __restrict__ wout,
                                                   const float* __restrict__ bout,
                                                   float* __restrict__ out)
{
    extern __shared__ float osh[];
    float* Xh = osh + OG_XH;
    float* Xl = osh + OG_XL;
    float* Wh = osh + OG_WH;
    float* Wl = osh + OG_WL;

    int t = threadIdx.x;
    int w = t >> 5, lane = t & 31, grp = lane >> 2, tig = lane & 3;
    int Rbase = blockIdx.x * 128;

    // load + split X tile (128 rows x 128 ch)
    for (int idx = t; idx < 4096; idx += 256) {
        int row = idx >> 5, c4 = idx & 31;
        float4 v = ((const float4*)d_outv)[(size_t)(Rbase + row)*32 + c4];
        float4 hi, lo;
        hi.x = __uint_as_float(tf32_(v.x)); lo.x = __uint_as_float(tf32_(v.x - hi.x));
        hi.y = __uint_as_float(tf32_(v.y)); lo.y = __uint_as_float(tf32_(v.y - hi.y));
        hi.z = __uint_as_float(tf32_(v.z)); lo.z = __uint_as_float(tf32_(v.z - hi.z));
        hi.w = __uint_as_float(tf32_(v.w)); lo.w = __uint_as_float(tf32_(v.w - hi.w));
        *(float4*)&Xh[row*OG_PX + 4*c4] = hi;
        *(float4*)&Xl[row*OG_PX + 4*c4] = lo;
    }
    // load + split W (64 o x 128 c)
    for (int idx = t; idx < 2048; idx += 256) {
        int o = idx >> 5, c4 = idx & 31;
        float4 v = ((const float4*)wout)[o*32 + c4];
        float4 hi, lo;
        hi.x = __uint_as_float(tf32_(v.x)); lo.x = __uint_as_float(tf32_(v.x - hi.x));
        hi.y = __uint_as_float(tf32_(v.y)); lo.y = __uint_as_float(tf32_(v.y - hi.y));
        hi.z = __uint_as_float(tf32_(v.z)); lo.z = __uint_as_float(tf32_(v.z - hi.z));
        hi.w = __uint_as_float(tf32_(v.w)); lo.w = __uint_as_float(tf32_(v.w - hi.w));
        *(float4*)&Wh[o*OG_PX + 4*c4] = hi;
        *(float4*)&Wl[o*OG_PX + 4*c4] = lo;
    }
    __syncthreads();

    // warp = m-tile (16 rows); acc over 8 n-tiles
    float acc[8][4];
#pragma unroll
    for (int nt = 0; nt < 8; nt++)
#pragma unroll
        for (int e = 0; e < 4; e++) acc[nt][e] = 0.f;

    int mrow0 = w*16 + grp;          // A frag rows: mrow0, mrow0+8
#pragma unroll 2
    for (int kc = 0; kc < 16; kc++) {
        uint ah[4], al[4];
#pragma unroll
        for (int e = 0; e < 4; e++) {
            int m = mrow0 + (e & 1)*8;
            int k = kc*8 + tig + (e >> 1)*4;
            ah[e] = __float_as_uint(Xh[m*OG_PX + k]);
            al[e] = __float_as_uint(Xl[m*OG_PX + k]);
        }
#pragma unroll
        for (int nt = 0; nt < 8; nt++) {
            int n = nt*8 + grp;
            int k = kc*8 + tig;
            uint bh0 = __float_as_uint(Wh[n*OG_PX + k]);
            uint bh1 = __float_as_uint(Wh[n*OG_PX + k + 4]);
            uint bl0 = __float_as_uint(Wl[n*OG_PX + k]);
            uint bl1 = __float_as_uint(Wl[n*OG_PX + k + 4]);
            MMA_TF32(acc[nt][0],acc[nt][1],acc[nt][2],acc[nt][3], ah[0],ah[1],ah[2],ah[3], bh0,bh1);
            MMA_TF32(acc[nt][0],acc[nt][1],acc[nt][2],acc[nt][3], ah[0],ah[1],ah[2],ah[3], bl0,bl1);
            MMA_TF32(acc[nt][0],acc[nt][1],acc[nt][2],acc[nt][3], al[0],al[1],al[2],al[3], bh0,bh1);
        }
    }

    // epilogue: C rows mrow0 / mrow0+8, cols nt*8 + 2*tig (+1)
    int R0 = Rbase + mrow0;
    int R1 = R0 + 8;
    int bb0 = R0 / (G*NPOS);  int rem0 = R0 - bb0*(G*NPOS);
    int g0  = rem0 / NPOS;    int pos0 = rem0 - g0*NPOS;
    int bb1 = R1 / (G*NPOS);  int rem1 = R1 - bb1*(G*NPOS);
    int g1  = rem1 / NPOS;    int pos1 = rem1 - g1*NPOS;
    size_t base0 = (size_t)bb0*(COUT*G*NPOS) + g0*NPOS + pos0;
    size_t base1 = (size_t)bb1*(COUT*G*NPOS) + g1*NPOS + pos1;

#pragma unroll
    for (int nt = 0; nt < 8; nt++) {
        int o0 = nt*8 + 2*tig;
        float bi0 = bout[o0], bi1 = bout[o0+1];
        out[base0 + (size_t)o0*(G*NPOS)]       = acc[nt][0] + bi0;
        out[base0 + (size_t)(o0+1)*(G*NPOS)]   = acc[nt][1] + bi1;
        out[base1 + (size_t)o0*(G*NPOS)]       = acc[nt][2] + bi0;
        out[base1 + (size_t)(o0+1)*(G*NPOS)]   = acc[nt][3] + bi1;
    }
}

// ---------------- launch ----------------
extern "C" void kernel_launch(void* const* d_in, const int* in_sizes, int n_in,
                              void* d_out, int out_size)
{
    const float* x     = (const float*)d_in[0];
    const float* wq    = (const float*)d_in[1];
    const float* bq    = (const float*)d_in[2];
    const float* wk    = (const float*)d_in[3];
    const float* bk    = (const float*)d_in[4];
    const float* wv    = (const float*)d_in[5];
    const float* bv    = (const float*)d_in[6];
    const float* w_out = (const float*)d_in[7];
    const float* b_out = (const float*)d_in[8];
    const float* row_w1 = (const float*)d_in[9];
    const float* row_b1 = (const float*)d_in[10];
    const float* row_g  = (const float*)d_in[11];
    const float* row_be = (const float*)d_in[12];
    const float* row_w2 = (const float*)d_in[13];
    const float* row_b2 = (const float*)d_in[14];
    const float* col_w1 = (const float*)d_in[15];
    const float* col_b1 = (const float*)d_in[16];
    const float* col_g  = (const float*)d_in[17];
    const float* col_be = (const float*)d_in[18];
    const float* col_w2 = (const float*)d_in[19];
    const float* col_b2 = (const float*)d_in[20];

    cudaFuncSetAttribute(attn_kernel, cudaFuncAttributeMaxDynamicSharedMemorySize, ATTN_SMEM_BYTES);
    cudaFuncSetAttribute(out_gemm,    cudaFuncAttributeMaxDynamicSharedMemorySize, OUT_SMEM_BYTES);

    qkv_embed_kernel<<<393, 256>>>(x, wq, bq, wk, bk, wv, bv,
                                   row_w1, row_b1, row_g, row_be, row_w2, row_b2,
                                   col_w1, col_b1, col_g, col_be, col_w2, col_b2);

    attn_kernel<<<BATCH*HEADS*14, 512, ATTN_SMEM_BYTES>>>();

    out_gemm<<<98, 256, OUT_SMEM_BYTES>>>(w_out, b_out, (float*)d_out);
}